// round 1
// baseline (speedup 1.0000x reference)
#include <cuda_runtime.h>
#include <cuda_bf16.h>

// Problem constants (from reference): N=200000, M=10000, K=16, T=40, F=32
#define M_NODES 10000
#define KNN     16
#define FSEM    32
#define EPSV    1e-8f

struct Quat { float w, x, y, z; };

__device__ __forceinline__ Quat qnormalize(Quat q) {
    float n2 = q.w * q.w + q.x * q.x + q.y * q.y + q.z * q.z;
    // reference clips norm at 1e-12 -> n2 at 1e-24
    float inv = rsqrtf(fmaxf(n2, 1e-24f));
    Quat r; r.w = q.w * inv; r.x = q.x * inv; r.y = q.y * inv; r.z = q.z * inv;
    return r;
}

__device__ __forceinline__ Quat qload(float4 v) {
    // memory layout (w, x, y, z)
    Quat q; q.w = v.x; q.x = v.y; q.y = v.z; q.z = v.w; return q;
}

// q assumed (near-)unit
__device__ __forceinline__ void q2R(Quat q, float R[3][3]) {
    float w = q.w, x = q.x, y = q.y, z = q.z;
    R[0][0] = 1.f - 2.f * (y * y + z * z);
    R[0][1] = 2.f * (x * y - w * z);
    R[0][2] = 2.f * (x * z + w * y);
    R[1][0] = 2.f * (x * y + w * z);
    R[1][1] = 1.f - 2.f * (x * x + z * z);
    R[1][2] = 2.f * (y * z - w * x);
    R[2][0] = 2.f * (x * z - w * y);
    R[2][1] = 2.f * (y * z + w * x);
    R[2][2] = 1.f - 2.f * (x * x + y * y);
}

__device__ __forceinline__ void mat3mul(const float A[3][3], const float B[3][3], float C[3][3]) {
    #pragma unroll
    for (int i = 0; i < 3; i++)
        #pragma unroll
        for (int j = 0; j < 3; j++)
            C[i][j] = A[i][0] * B[0][j] + A[i][1] * B[1][j] + A[i][2] * B[2][j];
}

// rotate v by unit quaternion q: v + w*t + u x t, t = 2*(u x v)
__device__ __forceinline__ float3 qrot(Quat q, float3 v) {
    float tx = 2.f * (q.y * v.z - q.z * v.y);
    float ty = 2.f * (q.z * v.x - q.x * v.z);
    float tz = 2.f * (q.x * v.y - q.y * v.x);
    float3 r;
    r.x = v.x + q.w * tx + (q.y * tz - q.z * ty);
    r.y = v.y + q.w * ty + (q.z * tx - q.x * tz);
    r.z = v.z + q.w * tz + (q.x * ty - q.y * tx);
    return r;
}

__device__ __forceinline__ float sigmoidf(float x) {
    return 1.f / (1.f + __expf(-x));
}

__global__ void __launch_bounds__(256)
dyn_scf_kernel(
    const float*  __restrict__ gs_xyz,     // (N,3)
    const float4* __restrict__ gs_rot,     // (N,4)
    const float*  __restrict__ gs_scal,    // (N,3)
    const float*  __restrict__ gs_op,      // (N,1)
    const float*  __restrict__ feat_dc,    // (N,3)
    const float*  __restrict__ feat_rest,  // (N,9)
    const float*  __restrict__ node_xyz,   // (T,M,3)
    const float4* __restrict__ node_quat,  // (T,M,4) as float4
    const float*  __restrict__ node_sigma, // (M,1)
    const float4* __restrict__ node_sem,   // (M,32) as M x 8 float4
    const int*    __restrict__ attach,     // (N,)
    const int*    __restrict__ ref_time,   // (N,)
    const int*    __restrict__ topo,       // (M,K)
    const int*    __restrict__ t_ptr,      // scalar
    float*        __restrict__ out,
    int N)
{
    int n = blockIdx.x * blockDim.x + threadIdx.x;
    if (n >= N) return;

    const int t  = (t_ptr != nullptr) ? __ldg(t_ptr) : 5;
    const int a  = attach[n];
    const int rt = ref_time[n];

    // ---- reference attach node ----
    const float* prp = node_xyz + ((long)rt * M_NODES + a) * 3;
    float3 pr = { prp[0], prp[1], prp[2] };
    Quat qa = qnormalize(qload(__ldg(&node_quat[(long)rt * M_NODES + a])));
    float Rr[3][3]; q2R(qa, Rr);

    float3 gx = { gs_xyz[3 * n], gs_xyz[3 * n + 1], gs_xyz[3 * n + 2] };
    float3 xw;
    xw.x = Rr[0][0] * gx.x + Rr[0][1] * gx.y + Rr[0][2] * gx.z + pr.x;
    xw.y = Rr[1][0] * gx.x + Rr[1][1] * gx.y + Rr[1][2] * gx.z + pr.y;
    xw.z = Rr[2][0] * gx.x + Rr[2][1] * gx.y + Rr[2][2] * gx.z + pr.z;

    Quat qg = qnormalize(qload(gs_rot[n]));
    float Rg[3][3]; q2R(qg, Rg);
    float Rw[3][3]; mat3mul(Rr, Rg, Rw);

    // ---- KNN skinning loop (single pass, unnormalized accumulation) ----
    const int* sk = topo + a * KNN;
    const float*  nx_ref  = node_xyz  + (long)rt * M_NODES * 3;
    const float*  nx_live = node_xyz  + (long)t  * M_NODES * 3;
    const float4* nq_ref  = node_quat + (long)rt * M_NODES;
    const float4* nq_live = node_quat + (long)t  * M_NODES;

    float S = 0.f;
    float3 mu = {0.f, 0.f, 0.f};
    Quat   qb = {0.f, 0.f, 0.f, 0.f};
    float4 sem[FSEM / 4];
    #pragma unroll
    for (int f = 0; f < FSEM / 4; f++) sem[f] = make_float4(0.f, 0.f, 0.f, 0.f);

    #pragma unroll 2
    for (int k = 0; k < KNN; k++) {
        int j = __ldg(&sk[k]);

        float3 pref = { __ldg(&nx_ref[3 * j]), __ldg(&nx_ref[3 * j + 1]), __ldg(&nx_ref[3 * j + 2]) };
        float3 d = { xw.x - pref.x, xw.y - pref.y, xw.z - pref.z };
        float dsq = d.x * d.x + d.y * d.y + d.z * d.z;

        float sig = __ldg(&node_sigma[j]);
        float wk  = __expf(-dsq / (2.f * sig * sig + EPSV));

        Quat qr = qnormalize(qload(__ldg(&nq_ref[j])));
        Quat ql = qnormalize(qload(__ldg(&nq_live[j])));
        // q_rel = ql * conj(qr)
        Quat q;
        q.w =  ql.w * qr.w + ql.x * qr.x + ql.y * qr.y + ql.z * qr.z;
        q.x = -ql.w * qr.x + ql.x * qr.w - ql.y * qr.z + ql.z * qr.y;
        q.y = -ql.w * qr.y + ql.x * qr.z + ql.y * qr.w - ql.z * qr.x;
        q.z = -ql.w * qr.z - ql.x * qr.y + ql.y * qr.x + ql.z * qr.w;

        float3 pl = { __ldg(&nx_live[3 * j]), __ldg(&nx_live[3 * j + 1]), __ldg(&nx_live[3 * j + 2]) };
        float3 mv = qrot(q, d);

        S    += wk;
        mu.x += wk * (mv.x + pl.x);
        mu.y += wk * (mv.y + pl.y);
        mu.z += wk * (mv.z + pl.z);
        qb.w += wk * q.w; qb.x += wk * q.x; qb.y += wk * q.y; qb.z += wk * q.z;

        const float4* sp = node_sem + (long)j * (FSEM / 4);
        #pragma unroll
        for (int f = 0; f < FSEM / 4; f++) {
            float4 v = __ldg(&sp[f]);
            sem[f].x += wk * v.x; sem[f].y += wk * v.y;
            sem[f].z += wk * v.z; sem[f].w += wk * v.w;
        }
    }

    float invS = 1.f / (S + EPSV);

    // fr_live = q2R(q_blend) @ R_world  (q2R renormalizes; invS factor cancels there,
    // but apply it anyway via qb for exactness of the normalize clip path)
    Quat qbn; qbn.w = qb.w * invS; qbn.x = qb.x * invS; qbn.y = qb.y * invS; qbn.z = qb.z * invS;
    qbn = qnormalize(qbn);
    float Rb[3][3]; q2R(qbn, Rb);
    float Fr[3][3]; mat3mul(Rb, Rw, Fr);

    // ---- outputs: concat of flattened (mu, fr, s, o, sph, sem) ----
    float* o_mu  = out;
    float* o_fr  = out + 3L  * N;
    float* o_s   = out + 12L * N;
    float* o_o   = out + 15L * N;
    float* o_sph = out + 16L * N;
    float* o_sem = out + 28L * N;

    o_mu[3 * n + 0] = mu.x * invS;
    o_mu[3 * n + 1] = mu.y * invS;
    o_mu[3 * n + 2] = mu.z * invS;

    #pragma unroll
    for (int i = 0; i < 3; i++)
        #pragma unroll
        for (int j = 0; j < 3; j++)
            o_fr[9 * n + 3 * i + j] = Fr[i][j];

    o_s[3 * n + 0] = 0.1f * sigmoidf(gs_scal[3 * n + 0]);
    o_s[3 * n + 1] = 0.1f * sigmoidf(gs_scal[3 * n + 1]);
    o_s[3 * n + 2] = 0.1f * sigmoidf(gs_scal[3 * n + 2]);

    o_o[n] = sigmoidf(gs_op[n]);

    #pragma unroll
    for (int i = 0; i < 3; i++) o_sph[12 * n + i] = feat_dc[3 * n + i];
    #pragma unroll
    for (int i = 0; i < 9; i++) o_sph[12 * n + 3 + i] = feat_rest[9 * n + i];

    float4* semo = (float4*)(o_sem) + (long)n * (FSEM / 4);
    #pragma unroll
    for (int f = 0; f < FSEM / 4; f++) {
        float4 v;
        v.x = sem[f].x * invS; v.y = sem[f].y * invS;
        v.z = sem[f].z * invS; v.w = sem[f].w * invS;
        semo[f] = v;
    }
}

extern "C" void kernel_launch(void* const* d_in, const int* in_sizes, int n_in,
                              void* d_out, int out_size) {
    const float*  gs_xyz     = (const float*)d_in[0];
    const float4* gs_rot     = (const float4*)d_in[1];
    const float*  gs_scal    = (const float*)d_in[2];
    const float*  gs_op      = (const float*)d_in[3];
    const float*  feat_dc    = (const float*)d_in[4];
    const float*  feat_rest  = (const float*)d_in[5];
    const float*  node_xyz   = (const float*)d_in[6];
    const float4* node_quat  = (const float4*)d_in[7];
    const float*  node_sigma = (const float*)d_in[8];
    const float4* node_sem   = (const float4*)d_in[9];
    const int*    attach     = (const int*)d_in[10];
    const int*    ref_time   = (const int*)d_in[11];
    const int*    topo       = (const int*)d_in[12];
    const int*    t_ptr      = (n_in > 13) ? (const int*)d_in[13] : nullptr;

    int N = in_sizes[0] / 3;

    int threads = 256;
    int blocks  = (N + threads - 1) / threads;
    dyn_scf_kernel<<<blocks, threads>>>(
        gs_xyz, gs_rot, gs_scal, gs_op, feat_dc, feat_rest,
        node_xyz, node_quat, node_sigma, node_sem,
        attach, ref_time, topo, t_ptr,
        (float*)d_out, N);
}

// round 3
// speedup vs baseline: 1.2231x; 1.2231x over previous
#include <cuda_runtime.h>
#include <cuda_bf16.h>

#define M_NODES 10000
#define KNN     16
#define FSEM    32
#define EPSV    1e-8f

struct Quat { float w, x, y, z; };

__device__ __forceinline__ Quat qnormalize(Quat q) {
    float n2 = q.w * q.w + q.x * q.x + q.y * q.y + q.z * q.z;
    float inv = rsqrtf(fmaxf(n2, 1e-24f));
    Quat r; r.w = q.w * inv; r.x = q.x * inv; r.y = q.y * inv; r.z = q.z * inv;
    return r;
}

__device__ __forceinline__ Quat qload(float4 v) {
    Quat q; q.w = v.x; q.x = v.y; q.y = v.z; q.z = v.w; return q;
}

__device__ __forceinline__ void q2R(Quat q, float R[3][3]) {
    float w = q.w, x = q.x, y = q.y, z = q.z;
    R[0][0] = 1.f - 2.f * (y * y + z * z);
    R[0][1] = 2.f * (x * y - w * z);
    R[0][2] = 2.f * (x * z + w * y);
    R[1][0] = 2.f * (x * y + w * z);
    R[1][1] = 1.f - 2.f * (x * x + z * z);
    R[1][2] = 2.f * (y * z - w * x);
    R[2][0] = 2.f * (x * z - w * y);
    R[2][1] = 2.f * (y * z + w * x);
    R[2][2] = 1.f - 2.f * (x * x + y * y);
}

__device__ __forceinline__ void mat3mul(const float A[3][3], const float B[3][3], float C[3][3]) {
    #pragma unroll
    for (int i = 0; i < 3; i++)
        #pragma unroll
        for (int j = 0; j < 3; j++)
            C[i][j] = A[i][0] * B[0][j] + A[i][1] * B[1][j] + A[i][2] * B[2][j];
}

__device__ __forceinline__ float3 qrot(Quat q, float3 v) {
    float tx = 2.f * (q.y * v.z - q.z * v.y);
    float ty = 2.f * (q.z * v.x - q.x * v.z);
    float tz = 2.f * (q.x * v.y - q.y * v.x);
    float3 r;
    r.x = v.x + q.w * tx + (q.y * tz - q.z * ty);
    r.y = v.y + q.w * ty + (q.z * tx - q.x * tz);
    r.z = v.z + q.w * tz + (q.x * ty - q.y * tx);
    return r;
}

__device__ __forceinline__ float sigmoidf(float x) {
    return 1.f / (1.f + __expf(-x));
}

__device__ __forceinline__ float warp_sum(float v) {
    #pragma unroll
    for (int o = 16; o >= 1; o >>= 1)
        v += __shfl_xor_sync(0xffffffffu, v, o);
    return v;
}

// ---- main kernel: one warp per gaussian ----
__global__ void __launch_bounds__(256)
dyn_scf_warp_kernel(
    const float*  __restrict__ gs_xyz,     // (N,3)
    const float4* __restrict__ gs_rot,     // (N,4)
    const float*  __restrict__ node_xyz,   // (T,M,3)
    const float4* __restrict__ node_quat,  // (T,M,4)
    const float*  __restrict__ node_sigma, // (M,1)
    const float*  __restrict__ node_sem,   // (M,32)
    const int*    __restrict__ attach,     // (N,)
    const int*    __restrict__ ref_time,   // (N,)
    const int*    __restrict__ topo,       // (M,K)
    const int*    __restrict__ t_ptr,
    float*        __restrict__ out,
    int N)
{
    const int warp_in_block = threadIdx.x >> 5;
    const int lane = threadIdx.x & 31;
    const int n = blockIdx.x * (blockDim.x >> 5) + warp_in_block;
    if (n >= N) return;

    const int t  = __ldg(t_ptr);
    const int a  = __ldg(&attach[n]);
    const int rt = __ldg(&ref_time[n]);

    // ---- preamble (all lanes redundantly; loads broadcast) ----
    const float* prp = node_xyz + ((long)rt * M_NODES + a) * 3;
    float3 pr = { __ldg(&prp[0]), __ldg(&prp[1]), __ldg(&prp[2]) };
    Quat qa = qnormalize(qload(__ldg(&node_quat[(long)rt * M_NODES + a])));
    float Rr[3][3]; q2R(qa, Rr);

    float3 gx = { __ldg(&gs_xyz[3 * n]), __ldg(&gs_xyz[3 * n + 1]), __ldg(&gs_xyz[3 * n + 2]) };
    float3 xw;
    xw.x = Rr[0][0] * gx.x + Rr[0][1] * gx.y + Rr[0][2] * gx.z + pr.x;
    xw.y = Rr[1][0] * gx.x + Rr[1][1] * gx.y + Rr[1][2] * gx.z + pr.y;
    xw.z = Rr[2][0] * gx.x + Rr[2][1] * gx.y + Rr[2][2] * gx.z + pr.z;

    Quat qg = qnormalize(qload(__ldg(&gs_rot[n])));
    float Rg[3][3]; q2R(qg, Rg);
    float Rw[3][3]; mat3mul(Rr, Rg, Rw);

    // ---- k-phase: lane (lane&15) owns neighbor k; lanes 16-31 duplicate, masked ----
    const int kl = lane & 15;
    const float maskv = (lane < 16) ? 1.f : 0.f;

    const int j = __ldg(&topo[a * KNN + kl]);

    const float*  nx_ref  = node_xyz  + (long)rt * M_NODES * 3;
    const float*  nx_live = node_xyz  + (long)t  * M_NODES * 3;

    float3 pref = { __ldg(&nx_ref[3 * j]), __ldg(&nx_ref[3 * j + 1]), __ldg(&nx_ref[3 * j + 2]) };
    float3 d = { xw.x - pref.x, xw.y - pref.y, xw.z - pref.z };
    float dsq = d.x * d.x + d.y * d.y + d.z * d.z;

    float sig = __ldg(&node_sigma[j]);
    float wk  = __expf(-dsq / (2.f * sig * sig + EPSV));
    float wm  = wk * maskv;   // masked weight (zero for upper half-warp)

    Quat qr = qnormalize(qload(__ldg(&node_quat[(long)rt * M_NODES + j])));
    Quat ql = qnormalize(qload(__ldg(&node_quat[(long)t  * M_NODES + j])));
    // q_rel = ql * conj(qr)
    Quat q;
    q.w =  ql.w * qr.w + ql.x * qr.x + ql.y * qr.y + ql.z * qr.z;
    q.x = -ql.w * qr.x + ql.x * qr.w - ql.y * qr.z + ql.z * qr.y;
    q.y = -ql.w * qr.y + ql.x * qr.z + ql.y * qr.w - ql.z * qr.x;
    q.z = -ql.w * qr.z - ql.x * qr.y + ql.y * qr.x + ql.z * qr.w;

    float3 pl = { __ldg(&nx_live[3 * j]), __ldg(&nx_live[3 * j + 1]), __ldg(&nx_live[3 * j + 2]) };
    float3 mv = qrot(q, d);

    // ---- warp reductions (all lanes end up with totals) ----
    float S   = warp_sum(wm);
    float mux = warp_sum(wm * (mv.x + pl.x));
    float muy = warp_sum(wm * (mv.y + pl.y));
    float muz = warp_sum(wm * (mv.z + pl.z));
    float qbw = warp_sum(wm * q.w);
    float qbx = warp_sum(wm * q.x);
    float qby = warp_sum(wm * q.y);
    float qbz = warp_sum(wm * q.z);

    float invS = 1.f / (S + EPSV);

    // ---- sem blend: lane = feature; per k, one coalesced 128B line ----
    float sem_acc = 0.f;
    #pragma unroll
    for (int k = 0; k < KNN; k++) {
        float wkk = __shfl_sync(0xffffffffu, wm, k);
        int   jk  = __shfl_sync(0xffffffffu, j,  k);
        sem_acc += wkk * __ldg(&node_sem[(long)jk * FSEM + lane]);
    }

    // ---- frame ----
    // CRITICAL: scale qb by invS BEFORE qnormalize. The reference normalizes the
    // weights (x ~invS) before its clip(norm, 1e-12); for rows with underflowing
    // weights (S ~ 1e-40..1e-20) the clip outcome DEPENDS on this scaling.
    Quat qbn; qbn.w = qbw * invS; qbn.x = qbx * invS; qbn.y = qby * invS; qbn.z = qbz * invS;
    qbn = qnormalize(qbn);
    float Rb[3][3]; q2R(qbn, Rb);
    float Fr[3][3]; mat3mul(Rb, Rw, Fr);

    // ---- outputs ----
    float* o_mu  = out;
    float* o_fr  = out + 3L  * N;
    float* o_sem = out + 28L * N;

    float muv = (lane == 0) ? mux : ((lane == 1) ? muy : muz);
    if (lane < 3) o_mu[3 * n + lane] = muv * invS;

    float frv = Fr[0][0];
    frv = (lane == 1) ? Fr[0][1] : frv;
    frv = (lane == 2) ? Fr[0][2] : frv;
    frv = (lane == 3) ? Fr[1][0] : frv;
    frv = (lane == 4) ? Fr[1][1] : frv;
    frv = (lane == 5) ? Fr[1][2] : frv;
    frv = (lane == 6) ? Fr[2][0] : frv;
    frv = (lane == 7) ? Fr[2][1] : frv;
    frv = (lane == 8) ? Fr[2][2] : frv;
    if (lane < 9) o_fr[9 * n + lane] = frv;

    o_sem[(long)n * FSEM + lane] = sem_acc * invS;
}

// ---- elementwise outputs: s, o, sph (fully coalesced) ----
__global__ void __launch_bounds__(256)
dyn_scf_elem_kernel(
    const float* __restrict__ gs_scal,   // (N,3)
    const float* __restrict__ gs_op,     // (N,1)
    const float* __restrict__ feat_dc,   // (N,3)
    const float* __restrict__ feat_rest, // (N,9)
    float*       __restrict__ out,
    int N)
{
    long e = (long)blockIdx.x * blockDim.x + threadIdx.x;
    long n3 = 3L * N, n12 = 12L * N;
    float* o_s   = out + 12L * N;
    float* o_o   = out + 15L * N;
    float* o_sph = out + 16L * N;

    if (e < n3) {
        o_s[e] = 0.1f * sigmoidf(__ldg(&gs_scal[e]));
    } else if (e < n3 + N) {
        long i = e - n3;
        o_o[i] = sigmoidf(__ldg(&gs_op[i]));
    } else if (e < n3 + N + n12) {
        long i = e - n3 - N;
        int n = (int)(i / 12);
        int c = (int)(i - 12L * n);
        o_sph[i] = (c < 3) ? __ldg(&feat_dc[3 * n + c]) : __ldg(&feat_rest[9 * n + c - 3]);
    }
}

extern "C" void kernel_launch(void* const* d_in, const int* in_sizes, int n_in,
                              void* d_out, int out_size) {
    const float*  gs_xyz     = (const float*)d_in[0];
    const float4* gs_rot     = (const float4*)d_in[1];
    const float*  gs_scal    = (const float*)d_in[2];
    const float*  gs_op      = (const float*)d_in[3];
    const float*  feat_dc    = (const float*)d_in[4];
    const float*  feat_rest  = (const float*)d_in[5];
    const float*  node_xyz   = (const float*)d_in[6];
    const float4* node_quat  = (const float4*)d_in[7];
    const float*  node_sigma = (const float*)d_in[8];
    const float*  node_sem   = (const float*)d_in[9];
    const int*    attach     = (const int*)d_in[10];
    const int*    ref_time   = (const int*)d_in[11];
    const int*    topo       = (const int*)d_in[12];
    const int*    t_ptr      = (const int*)d_in[13];

    int N = in_sizes[0] / 3;

    int gpb = 8;
    int blocks = (N + gpb - 1) / gpb;
    dyn_scf_warp_kernel<<<blocks, 256>>>(
        gs_xyz, gs_rot, node_xyz, node_quat, node_sigma, node_sem,
        attach, ref_time, topo, t_ptr, (float*)d_out, N);

    long total = 16L * N;
    int eblocks = (int)((total + 255) / 256);
    dyn_scf_elem_kernel<<<eblocks, 256>>>(
        gs_scal, gs_op, feat_dc, feat_rest, (float*)d_out, N);
}

// round 4
// speedup vs baseline: 1.6039x; 1.3114x over previous
#include <cuda_runtime.h>
#include <cuda_bf16.h>

#define M_NODES 10000
#define KNN     16
#define FSEM    32
#define EPSV    1e-8f

struct Quat { float w, x, y, z; };

__device__ __forceinline__ Quat qnormalize(Quat q) {
    float n2 = q.w * q.w + q.x * q.x + q.y * q.y + q.z * q.z;
    float inv = rsqrtf(fmaxf(n2, 1e-24f));
    Quat r; r.w = q.w * inv; r.x = q.x * inv; r.y = q.y * inv; r.z = q.z * inv;
    return r;
}

__device__ __forceinline__ Quat qload(float4 v) {
    Quat q; q.w = v.x; q.x = v.y; q.y = v.z; q.z = v.w; return q;
}

__device__ __forceinline__ void q2R(Quat q, float R[3][3]) {
    float w = q.w, x = q.x, y = q.y, z = q.z;
    R[0][0] = 1.f - 2.f * (y * y + z * z);
    R[0][1] = 2.f * (x * y - w * z);
    R[0][2] = 2.f * (x * z + w * y);
    R[1][0] = 2.f * (x * y + w * z);
    R[1][1] = 1.f - 2.f * (x * x + z * z);
    R[1][2] = 2.f * (y * z - w * x);
    R[2][0] = 2.f * (x * z - w * y);
    R[2][1] = 2.f * (y * z + w * x);
    R[2][2] = 1.f - 2.f * (x * x + y * y);
}

__device__ __forceinline__ void mat3mul(const float A[3][3], const float B[3][3], float C[3][3]) {
    #pragma unroll
    for (int i = 0; i < 3; i++)
        #pragma unroll
        for (int j = 0; j < 3; j++)
            C[i][j] = A[i][0] * B[0][j] + A[i][1] * B[1][j] + A[i][2] * B[2][j];
}

__device__ __forceinline__ float3 qrot(Quat q, float3 v) {
    float tx = 2.f * (q.y * v.z - q.z * v.y);
    float ty = 2.f * (q.z * v.x - q.x * v.z);
    float tz = 2.f * (q.x * v.y - q.y * v.x);
    float3 r;
    r.x = v.x + q.w * tx + (q.y * tz - q.z * ty);
    r.y = v.y + q.w * ty + (q.z * tx - q.x * tz);
    r.z = v.z + q.w * tz + (q.x * ty - q.y * tx);
    return r;
}

__device__ __forceinline__ float sigmoidf(float x) {
    return 1.f / (1.f + __expf(-x));
}

// butterfly sum within each 16-lane half-warp group
__device__ __forceinline__ float hw_sum(float v) {
    #pragma unroll
    for (int o = 8; o >= 1; o >>= 1)
        v += __shfl_xor_sync(0xffffffffu, v, o);
    return v;
}

// ---- main kernel: HALF-WARP (16 lanes) per gaussian; 2 gaussians per warp ----
__global__ void __launch_bounds__(256)
dyn_scf_hw_kernel(
    const float*  __restrict__ gs_xyz,     // (N,3)
    const float4* __restrict__ gs_rot,     // (N,4)
    const float*  __restrict__ node_xyz,   // (T,M,3)
    const float4* __restrict__ node_quat,  // (T,M,4)
    const float*  __restrict__ node_sigma, // (M,1)
    const float*  __restrict__ node_sem,   // (M,32)
    const int*    __restrict__ attach,     // (N,)
    const int*    __restrict__ ref_time,   // (N,)
    const int*    __restrict__ topo,       // (M,K)
    const int*    __restrict__ t_ptr,
    float*        __restrict__ out,
    int N)
{
    const int lane = threadIdx.x & 31;
    const int kl   = lane & 15;              // k owned by this lane within its group
    const int grp  = lane >> 4;              // 0 or 1: which gaussian in the warp
    const long warp_gid = (long)blockIdx.x * (blockDim.x >> 5) + (threadIdx.x >> 5);
    const int n = (int)(warp_gid * 2 + grp);
    if (n >= N) return;   // full warp exits together except at the very tail

    const int t  = __ldg(t_ptr);
    const int a  = __ldg(&attach[n]);
    const int rt = __ldg(&ref_time[n]);

    // ---- preamble (redundant within 16-lane group; 2 distinct gaussians/warp) ----
    const float* prp = node_xyz + ((long)rt * M_NODES + a) * 3;
    float3 pr = { __ldg(&prp[0]), __ldg(&prp[1]), __ldg(&prp[2]) };
    Quat qa = qnormalize(qload(__ldg(&node_quat[(long)rt * M_NODES + a])));
    float Rr[3][3]; q2R(qa, Rr);

    float3 gx = { __ldg(&gs_xyz[3 * n]), __ldg(&gs_xyz[3 * n + 1]), __ldg(&gs_xyz[3 * n + 2]) };
    float3 xw;
    xw.x = Rr[0][0] * gx.x + Rr[0][1] * gx.y + Rr[0][2] * gx.z + pr.x;
    xw.y = Rr[1][0] * gx.x + Rr[1][1] * gx.y + Rr[1][2] * gx.z + pr.y;
    xw.z = Rr[2][0] * gx.x + Rr[2][1] * gx.y + Rr[2][2] * gx.z + pr.z;

    Quat qg = qnormalize(qload(__ldg(&gs_rot[n])));
    float Rg[3][3]; q2R(qg, Rg);
    float Rw[3][3]; mat3mul(Rr, Rg, Rw);

    // ---- k-phase: every lane owns a distinct (gaussian, k) pair -> no masking ----
    const int j = __ldg(&topo[a * KNN + kl]);

    const float* nx_ref  = node_xyz + (long)rt * M_NODES * 3;
    const float* nx_live = node_xyz + (long)t  * M_NODES * 3;

    float3 pref = { __ldg(&nx_ref[3 * j]), __ldg(&nx_ref[3 * j + 1]), __ldg(&nx_ref[3 * j + 2]) };
    float3 d = { xw.x - pref.x, xw.y - pref.y, xw.z - pref.z };
    float dsq = d.x * d.x + d.y * d.y + d.z * d.z;

    float sig = __ldg(&node_sigma[j]);
    float wm  = __expf(-dsq / (2.f * sig * sig + EPSV));

    Quat qr = qnormalize(qload(__ldg(&node_quat[(long)rt * M_NODES + j])));
    Quat ql = qnormalize(qload(__ldg(&node_quat[(long)t  * M_NODES + j])));
    // q_rel = ql * conj(qr)
    Quat q;
    q.w =  ql.w * qr.w + ql.x * qr.x + ql.y * qr.y + ql.z * qr.z;
    q.x = -ql.w * qr.x + ql.x * qr.w - ql.y * qr.z + ql.z * qr.y;
    q.y = -ql.w * qr.y + ql.x * qr.z + ql.y * qr.w - ql.z * qr.x;
    q.z = -ql.w * qr.z - ql.x * qr.y + ql.y * qr.x + ql.z * qr.w;

    float3 pl = { __ldg(&nx_live[3 * j]), __ldg(&nx_live[3 * j + 1]), __ldg(&nx_live[3 * j + 2]) };
    float3 mv = qrot(q, d);

    // ---- group reductions (each serves both gaussians simultaneously) ----
    float S   = hw_sum(wm);
    float mux = hw_sum(wm * (mv.x + pl.x));
    float muy = hw_sum(wm * (mv.y + pl.y));
    float muz = hw_sum(wm * (mv.z + pl.z));
    float qbw = hw_sum(wm * q.w);
    float qbx = hw_sum(wm * q.x);
    float qby = hw_sum(wm * q.y);
    float qbz = hw_sum(wm * q.z);

    float invS = 1.f / (S + EPSV);

    // ---- sem blend: lane kl handles features kl and kl+16 of its gaussian ----
    const int src_base = lane & 16;   // group-relative shuffle base
    float sem0 = 0.f, sem1 = 0.f;
    #pragma unroll
    for (int k = 0; k < KNN; k++) {
        float wkk = __shfl_sync(0xffffffffu, wm, src_base | k);
        int   jk  = __shfl_sync(0xffffffffu, j,  src_base | k);
        const float* sp = node_sem + (long)jk * FSEM;
        sem0 += wkk * __ldg(&sp[kl]);
        sem1 += wkk * __ldg(&sp[kl + 16]);
    }

    // ---- frame ----
    // invS scaling BEFORE normalize is load-bearing: reference normalizes weights
    // before its clip(norm, 1e-12); for underflowing-weight rows the clip outcome
    // depends on this scaling (R2's 3.3e-2 failure).
    Quat qbn; qbn.w = qbw * invS; qbn.x = qbx * invS; qbn.y = qby * invS; qbn.z = qbz * invS;
    qbn = qnormalize(qbn);
    float Rb[3][3]; q2R(qbn, Rb);
    float Fr[3][3]; mat3mul(Rb, Rw, Fr);

    // ---- outputs ----
    float* o_mu  = out;
    float* o_fr  = out + 3L  * N;
    float* o_sem = out + 28L * N;

    float muv = (kl == 0) ? mux : ((kl == 1) ? muy : muz);
    if (kl < 3) o_mu[3 * n + kl] = muv * invS;

    float frv = Fr[0][0];
    frv = (kl == 1) ? Fr[0][1] : frv;
    frv = (kl == 2) ? Fr[0][2] : frv;
    frv = (kl == 3) ? Fr[1][0] : frv;
    frv = (kl == 4) ? Fr[1][1] : frv;
    frv = (kl == 5) ? Fr[1][2] : frv;
    frv = (kl == 6) ? Fr[2][0] : frv;
    frv = (kl == 7) ? Fr[2][1] : frv;
    frv = (kl == 8) ? Fr[2][2] : frv;
    if (kl < 9) o_fr[9 * n + kl] = frv;

    o_sem[(long)n * FSEM + kl]      = sem0 * invS;
    o_sem[(long)n * FSEM + kl + 16] = sem1 * invS;
}

// ---- elementwise outputs: s, o, sph — float4 vectorized ----
__global__ void __launch_bounds__(256)
dyn_scf_elem_kernel(
    const float4* __restrict__ gs_scal4,   // (N,3) as 3N/4 float4
    const float4* __restrict__ gs_op4,     // (N,)  as N/4 float4
    const float*  __restrict__ feat_dc,    // (N,3)
    const float*  __restrict__ feat_rest,  // (N,9)
    float*        __restrict__ out,
    int N)
{
    long e = (long)blockIdx.x * blockDim.x + threadIdx.x;
    const long ns4 = 3L * N / 4;       // float4 count for s
    const long no4 = (long)N / 4;      // float4 count for o
    float4* o_s4  = (float4*)(out + 12L * N);
    float4* o_o4  = (float4*)(out + 15L * N);
    float4* o_sph4 = (float4*)(out + 16L * N);

    if (e < ns4) {
        float4 v = __ldg(&gs_scal4[e]);
        v.x = 0.1f * sigmoidf(v.x); v.y = 0.1f * sigmoidf(v.y);
        v.z = 0.1f * sigmoidf(v.z); v.w = 0.1f * sigmoidf(v.w);
        o_s4[e] = v;
    } else if (e < ns4 + no4) {
        long i = e - ns4;
        float4 v = __ldg(&gs_op4[i]);
        v.x = sigmoidf(v.x); v.y = sigmoidf(v.y);
        v.z = sigmoidf(v.z); v.w = sigmoidf(v.w);
        o_o4[i] = v;
    } else if (e < ns4 + no4 + 3L * N) {
        long s4 = e - ns4 - no4;       // float4 index into sph region [0, 3N)
        int n = (int)(s4 / 3);
        int r = (int)(s4 - 3L * n);
        float4 v;
        const float* dc = feat_dc + 3 * n;
        const float* fr = feat_rest + 9 * n;
        if (r == 0) {
            v.x = __ldg(&dc[0]); v.y = __ldg(&dc[1]); v.z = __ldg(&dc[2]); v.w = __ldg(&fr[0]);
        } else if (r == 1) {
            v.x = __ldg(&fr[1]); v.y = __ldg(&fr[2]); v.z = __ldg(&fr[3]); v.w = __ldg(&fr[4]);
        } else {
            v.x = __ldg(&fr[5]); v.y = __ldg(&fr[6]); v.z = __ldg(&fr[7]); v.w = __ldg(&fr[8]);
        }
        o_sph4[s4] = v;
    }
}

extern "C" void kernel_launch(void* const* d_in, const int* in_sizes, int n_in,
                              void* d_out, int out_size) {
    const float*  gs_xyz     = (const float*)d_in[0];
    const float4* gs_rot     = (const float4*)d_in[1];
    const float4* gs_scal4   = (const float4*)d_in[2];
    const float4* gs_op4     = (const float4*)d_in[3];
    const float*  feat_dc    = (const float*)d_in[4];
    const float*  feat_rest  = (const float*)d_in[5];
    const float*  node_xyz   = (const float*)d_in[6];
    const float4* node_quat  = (const float4*)d_in[7];
    const float*  node_sigma = (const float*)d_in[8];
    const float*  node_sem   = (const float*)d_in[9];
    const int*    attach     = (const int*)d_in[10];
    const int*    ref_time   = (const int*)d_in[11];
    const int*    topo       = (const int*)d_in[12];
    const int*    t_ptr      = (const int*)d_in[13];

    int N = in_sizes[0] / 3;

    // main: 2 gaussians per warp, 8 warps per block -> 16 gaussians per block
    int blocks = (N + 15) / 16;
    dyn_scf_hw_kernel<<<blocks, 256>>>(
        gs_xyz, gs_rot, node_xyz, node_quat, node_sigma, node_sem,
        attach, ref_time, topo, t_ptr, (float*)d_out, N);

    // elementwise: 4N float4 units (3N/4 s + N/4 o + 3N sph)
    long total4 = (3L * N) / 4 + (long)N / 4 + 3L * N;
    int eblocks = (int)((total4 + 255) / 256);
    dyn_scf_elem_kernel<<<eblocks, 256>>>(
        gs_scal4, gs_op4, feat_dc, feat_rest, (float*)d_out, N);
}

// round 5
// speedup vs baseline: 1.7908x; 1.1165x over previous
#include <cuda_runtime.h>
#include <cuda_bf16.h>

#define M_NODES 10000
#define T_STEPS 40
#define KNN     16
#define FSEM    32
#define EPSV    1e-8f

// Precomputed per-(tt, j) tables: L2-resident, rebuilt every launch (deterministic).
__device__ float4 g_A[T_STEPS * M_NODES];  // (pref.x, pref.y, pref.z, 1/(2*sigma^2+eps))
__device__ float4 g_B[T_STEPS * M_NODES];  // q_rel = qnorm(q_live[t]) * conj(qnorm(q_ref[tt]))
__device__ float4 g_C[M_NODES];            // (p_live.x, p_live.y, p_live.z, 0)

struct Quat { float w, x, y, z; };

__device__ __forceinline__ Quat qnormalize(Quat q) {
    float n2 = q.w * q.w + q.x * q.x + q.y * q.y + q.z * q.z;
    float inv = rsqrtf(fmaxf(n2, 1e-24f));
    Quat r; r.w = q.w * inv; r.x = q.x * inv; r.y = q.y * inv; r.z = q.z * inv;
    return r;
}

__device__ __forceinline__ Quat qload(float4 v) {
    Quat q; q.w = v.x; q.x = v.y; q.y = v.z; q.z = v.w; return q;
}

__device__ __forceinline__ void q2R(Quat q, float R[3][3]) {
    float w = q.w, x = q.x, y = q.y, z = q.z;
    R[0][0] = 1.f - 2.f * (y * y + z * z);
    R[0][1] = 2.f * (x * y - w * z);
    R[0][2] = 2.f * (x * z + w * y);
    R[1][0] = 2.f * (x * y + w * z);
    R[1][1] = 1.f - 2.f * (x * x + z * z);
    R[1][2] = 2.f * (y * z - w * x);
    R[2][0] = 2.f * (x * z - w * y);
    R[2][1] = 2.f * (y * z + w * x);
    R[2][2] = 1.f - 2.f * (x * x + y * y);
}

__device__ __forceinline__ void mat3mul(const float A[3][3], const float B[3][3], float C[3][3]) {
    #pragma unroll
    for (int i = 0; i < 3; i++)
        #pragma unroll
        for (int j = 0; j < 3; j++)
            C[i][j] = A[i][0] * B[0][j] + A[i][1] * B[1][j] + A[i][2] * B[2][j];
}

__device__ __forceinline__ float3 qrot(Quat q, float3 v) {
    float tx = 2.f * (q.y * v.z - q.z * v.y);
    float ty = 2.f * (q.z * v.x - q.x * v.z);
    float tz = 2.f * (q.x * v.y - q.y * v.x);
    float3 r;
    r.x = v.x + q.w * tx + (q.y * tz - q.z * ty);
    r.y = v.y + q.w * ty + (q.z * tx - q.x * tz);
    r.z = v.z + q.w * tz + (q.x * ty - q.y * tx);
    return r;
}

__device__ __forceinline__ float sigmoidf(float x) {
    return 1.f / (1.f + __expf(-x));
}

__device__ __forceinline__ float hw_sum(float v) {
    #pragma unroll
    for (int o = 8; o >= 1; o >>= 1)
        v += __shfl_xor_sync(0xffffffffu, v, o);
    return v;
}

// ---- precompute kernel: one thread per (tt, j) ----
__global__ void __launch_bounds__(256)
dyn_scf_pre_kernel(
    const float*  __restrict__ node_xyz,   // (T,M,3)
    const float4* __restrict__ node_quat,  // (T,M,4)
    const float*  __restrict__ node_sigma, // (M,1)
    const int*    __restrict__ t_ptr)
{
    int idx = blockIdx.x * blockDim.x + threadIdx.x;
    if (idx >= T_STEPS * M_NODES) return;
    int j  = idx % M_NODES;
    int tt = idx / M_NODES;
    int t  = __ldg(t_ptr);

    Quat qr = qnormalize(qload(__ldg(&node_quat[idx])));
    Quat ql = qnormalize(qload(__ldg(&node_quat[(long)t * M_NODES + j])));
    // q_rel = ql * conj(qr)
    float4 B;
    B.x =  ql.w * qr.w + ql.x * qr.x + ql.y * qr.y + ql.z * qr.z;  // w
    B.y = -ql.w * qr.x + ql.x * qr.w - ql.y * qr.z + ql.z * qr.y;  // x
    B.z = -ql.w * qr.y + ql.x * qr.z + ql.y * qr.w - ql.z * qr.x;  // y
    B.w = -ql.w * qr.z - ql.x * qr.y + ql.y * qr.x + ql.z * qr.w;  // z
    g_B[idx] = B;

    float sig = __ldg(&node_sigma[j]);
    float px = __ldg(&node_xyz[3L * idx]);
    float py = __ldg(&node_xyz[3L * idx + 1]);
    float pz = __ldg(&node_xyz[3L * idx + 2]);
    g_A[idx] = make_float4(px, py, pz, 1.f / (2.f * sig * sig + EPSV));
    if (tt == t) g_C[j] = make_float4(px, py, pz, 0.f);
}

// ---- main kernel: half-warp (16 lanes) per gaussian; 2 gaussians per warp ----
__global__ void __launch_bounds__(256)
dyn_scf_hw_kernel(
    const float*  __restrict__ gs_xyz,     // (N,3)
    const float4* __restrict__ gs_rot,     // (N,4)
    const float4* __restrict__ node_quat,  // (T,M,4)
    const float2* __restrict__ node_sem2,  // (M,32) as M x 16 float2
    const int*    __restrict__ attach,     // (N,)
    const int*    __restrict__ ref_time,   // (N,)
    const int*    __restrict__ topo,       // (M,K)
    float*        __restrict__ out,
    int N)
{
    const int lane = threadIdx.x & 31;
    const int kl   = lane & 15;
    const int grp  = lane >> 4;
    const long warp_gid = (long)blockIdx.x * (blockDim.x >> 5) + (threadIdx.x >> 5);
    const int n = (int)(warp_gid * 2 + grp);
    if (n >= N) return;

    const int a  = __ldg(&attach[n]);
    const int rt = __ldg(&ref_time[n]);
    const long rtM = (long)rt * M_NODES;

    // ---- preamble ----
    float4 Aa = __ldg(&g_A[rtM + a]);                 // attach node ref pos
    Quat qa = qnormalize(qload(__ldg(&node_quat[rtM + a])));
    float Rr[3][3]; q2R(qa, Rr);

    float3 gx = { __ldg(&gs_xyz[3 * n]), __ldg(&gs_xyz[3 * n + 1]), __ldg(&gs_xyz[3 * n + 2]) };
    float3 xw;
    xw.x = Rr[0][0] * gx.x + Rr[0][1] * gx.y + Rr[0][2] * gx.z + Aa.x;
    xw.y = Rr[1][0] * gx.x + Rr[1][1] * gx.y + Rr[1][2] * gx.z + Aa.y;
    xw.z = Rr[2][0] * gx.x + Rr[2][1] * gx.y + Rr[2][2] * gx.z + Aa.z;

    Quat qg = qnormalize(qload(__ldg(&gs_rot[n])));
    float Rg[3][3]; q2R(qg, Rg);
    float Rw[3][3]; mat3mul(Rr, Rg, Rw);

    // ---- k-phase: 3 float4 gathers per lane ----
    const int j = __ldg(&topo[a * KNN + kl]);

    float4 Ai = __ldg(&g_A[rtM + j]);
    float3 d = { xw.x - Ai.x, xw.y - Ai.y, xw.z - Ai.z };
    float dsq = d.x * d.x + d.y * d.y + d.z * d.z;
    float wm  = __expf(-dsq * Ai.w);

    float4 Bi = __ldg(&g_B[rtM + j]);
    Quat q; q.w = Bi.x; q.x = Bi.y; q.y = Bi.z; q.z = Bi.w;

    float4 Ci = __ldg(&g_C[j]);
    float3 mv = qrot(q, d);

    // ---- group reductions (serve both gaussians of the warp at once) ----
    float S   = hw_sum(wm);
    float mux = hw_sum(wm * (mv.x + Ci.x));
    float muy = hw_sum(wm * (mv.y + Ci.y));
    float muz = hw_sum(wm * (mv.z + Ci.z));
    float qbw = hw_sum(wm * q.w);
    float qbx = hw_sum(wm * q.x);
    float qby = hw_sum(wm * q.y);
    float qbz = hw_sum(wm * q.z);

    float invS = 1.f / (S + EPSV);

    // ---- sem blend: lane kl owns features {2kl, 2kl+1}; float2 loads/stores ----
    const int src_base = lane & 16;
    float s0 = 0.f, s1 = 0.f;
    #pragma unroll
    for (int k = 0; k < KNN; k++) {
        float wkk = __shfl_sync(0xffffffffu, wm, src_base | k);
        int   jk  = __shfl_sync(0xffffffffu, j,  src_base | k);
        float2 v = __ldg(&node_sem2[(long)jk * (FSEM / 2) + kl]);
        s0 += wkk * v.x;
        s1 += wkk * v.y;
    }

    // ---- frame (invS scaling BEFORE normalize is load-bearing: clip semantics) ----
    Quat qbn; qbn.w = qbw * invS; qbn.x = qbx * invS; qbn.y = qby * invS; qbn.z = qbz * invS;
    qbn = qnormalize(qbn);
    float Rb[3][3]; q2R(qbn, Rb);
    float Fr[3][3]; mat3mul(Rb, Rw, Fr);

    // ---- outputs ----
    float*  o_mu  = out;
    float*  o_fr  = out + 3L  * N;
    float2* o_sem = (float2*)(out + 28L * N);

    float muv = (kl == 0) ? mux : ((kl == 1) ? muy : muz);
    if (kl < 3) o_mu[3 * n + kl] = muv * invS;

    float frv = Fr[0][0];
    frv = (kl == 1) ? Fr[0][1] : frv;
    frv = (kl == 2) ? Fr[0][2] : frv;
    frv = (kl == 3) ? Fr[1][0] : frv;
    frv = (kl == 4) ? Fr[1][1] : frv;
    frv = (kl == 5) ? Fr[1][2] : frv;
    frv = (kl == 6) ? Fr[2][0] : frv;
    frv = (kl == 7) ? Fr[2][1] : frv;
    frv = (kl == 8) ? Fr[2][2] : frv;
    if (kl < 9) o_fr[9 * n + kl] = frv;

    o_sem[(long)n * (FSEM / 2) + kl] = make_float2(s0 * invS, s1 * invS);
}

// ---- elementwise outputs: s, o, sph — float4 vectorized ----
__global__ void __launch_bounds__(256)
dyn_scf_elem_kernel(
    const float4* __restrict__ gs_scal4,
    const float4* __restrict__ gs_op4,
    const float*  __restrict__ feat_dc,
    const float*  __restrict__ feat_rest,
    float*        __restrict__ out,
    int N)
{
    long e = (long)blockIdx.x * blockDim.x + threadIdx.x;
    const long ns4 = 3L * N / 4;
    const long no4 = (long)N / 4;
    float4* o_s4   = (float4*)(out + 12L * N);
    float4* o_o4   = (float4*)(out + 15L * N);
    float4* o_sph4 = (float4*)(out + 16L * N);

    if (e < ns4) {
        float4 v = __ldg(&gs_scal4[e]);
        v.x = 0.1f * sigmoidf(v.x); v.y = 0.1f * sigmoidf(v.y);
        v.z = 0.1f * sigmoidf(v.z); v.w = 0.1f * sigmoidf(v.w);
        o_s4[e] = v;
    } else if (e < ns4 + no4) {
        long i = e - ns4;
        float4 v = __ldg(&gs_op4[i]);
        v.x = sigmoidf(v.x); v.y = sigmoidf(v.y);
        v.z = sigmoidf(v.z); v.w = sigmoidf(v.w);
        o_o4[i] = v;
    } else if (e < ns4 + no4 + 3L * N) {
        long s4 = e - ns4 - no4;
        int n = (int)(s4 / 3);
        int r = (int)(s4 - 3L * n);
        float4 v;
        const float* dc = feat_dc + 3 * n;
        const float* fr = feat_rest + 9 * n;
        if (r == 0) {
            v.x = __ldg(&dc[0]); v.y = __ldg(&dc[1]); v.z = __ldg(&dc[2]); v.w = __ldg(&fr[0]);
        } else if (r == 1) {
            v.x = __ldg(&fr[1]); v.y = __ldg(&fr[2]); v.z = __ldg(&fr[3]); v.w = __ldg(&fr[4]);
        } else {
            v.x = __ldg(&fr[5]); v.y = __ldg(&fr[6]); v.z = __ldg(&fr[7]); v.w = __ldg(&fr[8]);
        }
        o_sph4[s4] = v;
    }
}

extern "C" void kernel_launch(void* const* d_in, const int* in_sizes, int n_in,
                              void* d_out, int out_size) {
    const float*  gs_xyz     = (const float*)d_in[0];
    const float4* gs_rot     = (const float4*)d_in[1];
    const float4* gs_scal4   = (const float4*)d_in[2];
    const float4* gs_op4     = (const float4*)d_in[3];
    const float*  feat_dc    = (const float*)d_in[4];
    const float*  feat_rest  = (const float*)d_in[5];
    const float*  node_xyz   = (const float*)d_in[6];
    const float4* node_quat  = (const float4*)d_in[7];
    const float*  node_sigma = (const float*)d_in[8];
    const float2* node_sem2  = (const float2*)d_in[9];
    const int*    attach     = (const int*)d_in[10];
    const int*    ref_time   = (const int*)d_in[11];
    const int*    topo       = (const int*)d_in[12];
    const int*    t_ptr      = (const int*)d_in[13];

    int N = in_sizes[0] / 3;

    // Launch order chosen so ncu (-s 5 -c 1) captures the MAIN kernel (index 5).
    long total4 = (3L * N) / 4 + (long)N / 4 + 3L * N;
    int eblocks = (int)((total4 + 255) / 256);
    dyn_scf_elem_kernel<<<eblocks, 256>>>(
        gs_scal4, gs_op4, feat_dc, feat_rest, (float*)d_out, N);

    int pblocks = (T_STEPS * M_NODES + 255) / 256;
    dyn_scf_pre_kernel<<<pblocks, 256>>>(node_xyz, node_quat, node_sigma, t_ptr);

    int blocks = (N + 15) / 16;
    dyn_scf_hw_kernel<<<blocks, 256>>>(
        gs_xyz, gs_rot, node_quat, node_sem2,
        attach, ref_time, topo, (float*)d_out, N);
}

// round 6
// speedup vs baseline: 2.4072x; 1.3442x over previous
#include <cuda_runtime.h>
#include <cuda_bf16.h>

#define M_NODES 10000
#define T_STEPS 40
#define KNN     16
#define FSEM    32
#define EPSV    1e-8f

// Precomputed per-(tt, j) tables: L2-resident, rebuilt every launch (deterministic).
__device__ float4 g_A[T_STEPS * M_NODES];  // (pref.x, pref.y, pref.z, 1/(2*sigma^2+eps))
__device__ float4 g_B[T_STEPS * M_NODES];  // q_rel = qnorm(q_live[t]) * conj(qnorm(q_ref[tt]))
__device__ float4 g_C[M_NODES];            // (p_live.x, p_live.y, p_live.z, 0)

struct Quat { float w, x, y, z; };

__device__ __forceinline__ Quat qnormalize(Quat q) {
    float n2 = q.w * q.w + q.x * q.x + q.y * q.y + q.z * q.z;
    float inv = rsqrtf(fmaxf(n2, 1e-24f));
    Quat r; r.w = q.w * inv; r.x = q.x * inv; r.y = q.y * inv; r.z = q.z * inv;
    return r;
}

__device__ __forceinline__ Quat qload(float4 v) {
    Quat q; q.w = v.x; q.x = v.y; q.y = v.z; q.z = v.w; return q;
}

__device__ __forceinline__ void q2R(Quat q, float R[3][3]) {
    float w = q.w, x = q.x, y = q.y, z = q.z;
    R[0][0] = 1.f - 2.f * (y * y + z * z);
    R[0][1] = 2.f * (x * y - w * z);
    R[0][2] = 2.f * (x * z + w * y);
    R[1][0] = 2.f * (x * y + w * z);
    R[1][1] = 1.f - 2.f * (x * x + z * z);
    R[1][2] = 2.f * (y * z - w * x);
    R[2][0] = 2.f * (x * z - w * y);
    R[2][1] = 2.f * (y * z + w * x);
    R[2][2] = 1.f - 2.f * (x * x + y * y);
}

__device__ __forceinline__ void mat3mul(const float A[3][3], const float B[3][3], float C[3][3]) {
    #pragma unroll
    for (int i = 0; i < 3; i++)
        #pragma unroll
        for (int j = 0; j < 3; j++)
            C[i][j] = A[i][0] * B[0][j] + A[i][1] * B[1][j] + A[i][2] * B[2][j];
}

__device__ __forceinline__ float3 qrot(Quat q, float3 v) {
    float tx = 2.f * (q.y * v.z - q.z * v.y);
    float ty = 2.f * (q.z * v.x - q.x * v.z);
    float tz = 2.f * (q.x * v.y - q.y * v.x);
    float3 r;
    r.x = v.x + q.w * tx + (q.y * tz - q.z * ty);
    r.y = v.y + q.w * ty + (q.z * tx - q.x * tz);
    r.z = v.z + q.w * tz + (q.x * ty - q.y * tx);
    return r;
}

__device__ __forceinline__ float sigmoidf(float x) {
    return 1.f / (1.f + __expf(-x));
}

// butterfly sum within each 8-lane quarter-warp group
__device__ __forceinline__ float qw_sum(float v) {
    v += __shfl_xor_sync(0xffffffffu, v, 4);
    v += __shfl_xor_sync(0xffffffffu, v, 2);
    v += __shfl_xor_sync(0xffffffffu, v, 1);
    return v;
}

// ---- precompute kernel: one thread per (tt, j) ----
__global__ void __launch_bounds__(256)
dyn_scf_pre_kernel(
    const float*  __restrict__ node_xyz,   // (T,M,3)
    const float4* __restrict__ node_quat,  // (T,M,4)
    const float*  __restrict__ node_sigma, // (M,1)
    const int*    __restrict__ t_ptr)
{
    int idx = blockIdx.x * blockDim.x + threadIdx.x;
    if (idx >= T_STEPS * M_NODES) return;
    int j  = idx % M_NODES;
    int tt = idx / M_NODES;
    int t  = __ldg(t_ptr);

    Quat qr = qnormalize(qload(__ldg(&node_quat[idx])));
    Quat ql = qnormalize(qload(__ldg(&node_quat[(long)t * M_NODES + j])));
    // q_rel = ql * conj(qr)
    float4 B;
    B.x =  ql.w * qr.w + ql.x * qr.x + ql.y * qr.y + ql.z * qr.z;
    B.y = -ql.w * qr.x + ql.x * qr.w - ql.y * qr.z + ql.z * qr.y;
    B.z = -ql.w * qr.y + ql.x * qr.z + ql.y * qr.w - ql.z * qr.x;
    B.w = -ql.w * qr.z - ql.x * qr.y + ql.y * qr.x + ql.z * qr.w;
    g_B[idx] = B;

    float sig = __ldg(&node_sigma[j]);
    float px = __ldg(&node_xyz[3L * idx]);
    float py = __ldg(&node_xyz[3L * idx + 1]);
    float pz = __ldg(&node_xyz[3L * idx + 2]);
    g_A[idx] = make_float4(px, py, pz, 1.f / (2.f * sig * sig + EPSV));
    if (tt == t) g_C[j] = make_float4(px, py, pz, 0.f);
}

// ---- main kernel: quarter-warp (8 lanes) per gaussian; 4 gaussians per warp ----
// Each lane owns neighbors k=kl and k=kl+8.
__global__ void __launch_bounds__(256)
dyn_scf_qw_kernel(
    const float*  __restrict__ gs_xyz,     // (N,3)
    const float4* __restrict__ gs_rot,     // (N,4)
    const float4* __restrict__ node_quat,  // (T,M,4)
    const float4* __restrict__ node_sem4,  // (M,32) as M x 8 float4
    const int*    __restrict__ attach,     // (N,)
    const int*    __restrict__ ref_time,   // (N,)
    const int*    __restrict__ topo,       // (M,K)
    float*        __restrict__ out,
    int N)
{
    const int lane = threadIdx.x & 31;
    const int kl   = lane & 7;               // lane within 8-lane group
    const int grp  = (lane >> 3) & 3;        // gaussian slot within warp
    const long warp_gid = (long)blockIdx.x * (blockDim.x >> 5) + (threadIdx.x >> 5);
    const int n = (int)(warp_gid * 4 + grp);
    if (n >= N) return;   // N % 32 == 0 for this problem -> never partial

    const int a  = __ldg(&attach[n]);
    const int rt = __ldg(&ref_time[n]);
    const long rtM = (long)rt * M_NODES;

    // ---- preamble (redundant across 8 lanes; 4 distinct gaussians/warp) ----
    float4 Aa = __ldg(&g_A[rtM + a]);
    Quat qa = qnormalize(qload(__ldg(&node_quat[rtM + a])));
    float Rr[3][3]; q2R(qa, Rr);

    float3 gx = { __ldg(&gs_xyz[3 * n]), __ldg(&gs_xyz[3 * n + 1]), __ldg(&gs_xyz[3 * n + 2]) };
    float3 xw;
    xw.x = Rr[0][0] * gx.x + Rr[0][1] * gx.y + Rr[0][2] * gx.z + Aa.x;
    xw.y = Rr[1][0] * gx.x + Rr[1][1] * gx.y + Rr[1][2] * gx.z + Aa.y;
    xw.z = Rr[2][0] * gx.x + Rr[2][1] * gx.y + Rr[2][2] * gx.z + Aa.z;

    Quat qg = qnormalize(qload(__ldg(&gs_rot[n])));
    float Rg[3][3]; q2R(qg, Rg);
    float Rw[3][3]; mat3mul(Rr, Rg, Rw);

    // ---- k-phase: this lane handles k0=kl and k1=kl+8 ----
    const int j0 = __ldg(&topo[a * KNN + kl]);
    const int j1 = __ldg(&topo[a * KNN + kl + 8]);

    float4 A0 = __ldg(&g_A[rtM + j0]);
    float4 A1 = __ldg(&g_A[rtM + j1]);
    float4 B0 = __ldg(&g_B[rtM + j0]);
    float4 B1 = __ldg(&g_B[rtM + j1]);
    float4 C0 = __ldg(&g_C[j0]);
    float4 C1 = __ldg(&g_C[j1]);

    float3 d0 = { xw.x - A0.x, xw.y - A0.y, xw.z - A0.z };
    float3 d1 = { xw.x - A1.x, xw.y - A1.y, xw.z - A1.z };
    float w0 = __expf(-(d0.x * d0.x + d0.y * d0.y + d0.z * d0.z) * A0.w);
    float w1 = __expf(-(d1.x * d1.x + d1.y * d1.y + d1.z * d1.z) * A1.w);

    Quat q0; q0.w = B0.x; q0.x = B0.y; q0.y = B0.z; q0.z = B0.w;
    Quat q1; q1.w = B1.x; q1.x = B1.y; q1.y = B1.z; q1.z = B1.w;
    float3 m0 = qrot(q0, d0);
    float3 m1 = qrot(q1, d1);

    // local pair-sums, then 3-level butterfly (serves all 4 gaussians at once)
    float S   = qw_sum(w0 + w1);
    float mux = qw_sum(w0 * (m0.x + C0.x) + w1 * (m1.x + C1.x));
    float muy = qw_sum(w0 * (m0.y + C0.y) + w1 * (m1.y + C1.y));
    float muz = qw_sum(w0 * (m0.z + C0.z) + w1 * (m1.z + C1.z));
    float qbw = qw_sum(w0 * q0.w + w1 * q1.w);
    float qbx = qw_sum(w0 * q0.x + w1 * q1.x);
    float qby = qw_sum(w0 * q0.y + w1 * q1.y);
    float qbz = qw_sum(w0 * q0.z + w1 * q1.z);

    float invS = 1.f / (S + EPSV);

    // ---- sem blend: lane kl owns features [4kl, 4kl+4); one 128B line per group per k ----
    const int src_base = lane & 24;   // group base lane
    float4 sacc = make_float4(0.f, 0.f, 0.f, 0.f);
    #pragma unroll
    for (int k = 0; k < 8; k++) {
        float wk = __shfl_sync(0xffffffffu, w0, src_base | k);
        int   jk = __shfl_sync(0xffffffffu, j0, src_base | k);
        float4 v = __ldg(&node_sem4[(long)jk * (FSEM / 4) + kl]);
        sacc.x += wk * v.x; sacc.y += wk * v.y; sacc.z += wk * v.z; sacc.w += wk * v.w;
    }
    #pragma unroll
    for (int k = 0; k < 8; k++) {
        float wk = __shfl_sync(0xffffffffu, w1, src_base | k);
        int   jk = __shfl_sync(0xffffffffu, j1, src_base | k);
        float4 v = __ldg(&node_sem4[(long)jk * (FSEM / 4) + kl]);
        sacc.x += wk * v.x; sacc.y += wk * v.y; sacc.z += wk * v.z; sacc.w += wk * v.w;
    }

    // ---- frame (invS scaling BEFORE normalize is load-bearing: clip semantics) ----
    Quat qbn; qbn.w = qbw * invS; qbn.x = qbx * invS; qbn.y = qby * invS; qbn.z = qbz * invS;
    qbn = qnormalize(qbn);
    float Rb[3][3]; q2R(qbn, Rb);
    float Fr[3][3]; mat3mul(Rb, Rw, Fr);

    // ---- outputs ----
    float*  o_mu  = out;
    float*  o_fr  = out + 3L  * N;
    float4* o_sem = (float4*)(out + 28L * N);

    float muv = (kl == 0) ? mux : ((kl == 1) ? muy : muz);
    if (kl < 3) o_mu[3 * n + kl] = muv * invS;

    // fr: 9 elements over 8 lanes; lane 0 writes elements 0 and 8
    float frv = Fr[0][0];
    frv = (kl == 1) ? Fr[0][1] : frv;
    frv = (kl == 2) ? Fr[0][2] : frv;
    frv = (kl == 3) ? Fr[1][0] : frv;
    frv = (kl == 4) ? Fr[1][1] : frv;
    frv = (kl == 5) ? Fr[1][2] : frv;
    frv = (kl == 6) ? Fr[2][0] : frv;
    frv = (kl == 7) ? Fr[2][1] : frv;
    o_fr[9 * n + kl] = frv;
    if (kl == 0) o_fr[9 * n + 8] = Fr[2][2];

    float4 sv; sv.x = sacc.x * invS; sv.y = sacc.y * invS;
    sv.z = sacc.z * invS; sv.w = sacc.w * invS;
    o_sem[(long)n * (FSEM / 4) + kl] = sv;
}

// ---- elementwise outputs: s, o, sph — float4 vectorized ----
__global__ void __launch_bounds__(256)
dyn_scf_elem_kernel(
    const float4* __restrict__ gs_scal4,
    const float4* __restrict__ gs_op4,
    const float*  __restrict__ feat_dc,
    const float*  __restrict__ feat_rest,
    float*        __restrict__ out,
    int N)
{
    long e = (long)blockIdx.x * blockDim.x + threadIdx.x;
    const long ns4 = 3L * N / 4;
    const long no4 = (long)N / 4;
    float4* o_s4   = (float4*)(out + 12L * N);
    float4* o_o4   = (float4*)(out + 15L * N);
    float4* o_sph4 = (float4*)(out + 16L * N);

    if (e < ns4) {
        float4 v = __ldg(&gs_scal4[e]);
        v.x = 0.1f * sigmoidf(v.x); v.y = 0.1f * sigmoidf(v.y);
        v.z = 0.1f * sigmoidf(v.z); v.w = 0.1f * sigmoidf(v.w);
        o_s4[e] = v;
    } else if (e < ns4 + no4) {
        long i = e - ns4;
        float4 v = __ldg(&gs_op4[i]);
        v.x = sigmoidf(v.x); v.y = sigmoidf(v.y);
        v.z = sigmoidf(v.z); v.w = sigmoidf(v.w);
        o_o4[i] = v;
    } else if (e < ns4 + no4 + 3L * N) {
        long s4 = e - ns4 - no4;
        int n = (int)(s4 / 3);
        int r = (int)(s4 - 3L * n);
        float4 v;
        const float* dc = feat_dc + 3 * n;
        const float* fr = feat_rest + 9 * n;
        if (r == 0) {
            v.x = __ldg(&dc[0]); v.y = __ldg(&dc[1]); v.z = __ldg(&dc[2]); v.w = __ldg(&fr[0]);
        } else if (r == 1) {
            v.x = __ldg(&fr[1]); v.y = __ldg(&fr[2]); v.z = __ldg(&fr[3]); v.w = __ldg(&fr[4]);
        } else {
            v.x = __ldg(&fr[5]); v.y = __ldg(&fr[6]); v.z = __ldg(&fr[7]); v.w = __ldg(&fr[8]);
        }
        o_sph4[s4] = v;
    }
}

extern "C" void kernel_launch(void* const* d_in, const int* in_sizes, int n_in,
                              void* d_out, int out_size) {
    const float*  gs_xyz     = (const float*)d_in[0];
    const float4* gs_rot     = (const float4*)d_in[1];
    const float4* gs_scal4   = (const float4*)d_in[2];
    const float4* gs_op4     = (const float4*)d_in[3];
    const float*  feat_dc    = (const float*)d_in[4];
    const float*  feat_rest  = (const float*)d_in[5];
    const float*  node_xyz   = (const float*)d_in[6];
    const float4* node_quat  = (const float4*)d_in[7];
    const float*  node_sigma = (const float*)d_in[8];
    const float4* node_sem4  = (const float4*)d_in[9];
    const int*    attach     = (const int*)d_in[10];
    const int*    ref_time   = (const int*)d_in[11];
    const int*    topo       = (const int*)d_in[12];
    const int*    t_ptr      = (const int*)d_in[13];

    int N = in_sizes[0] / 3;

    long total4 = (3L * N) / 4 + (long)N / 4 + 3L * N;
    int eblocks = (int)((total4 + 255) / 256);
    dyn_scf_elem_kernel<<<eblocks, 256>>>(
        gs_scal4, gs_op4, feat_dc, feat_rest, (float*)d_out, N);

    int pblocks = (T_STEPS * M_NODES + 255) / 256;
    dyn_scf_pre_kernel<<<pblocks, 256>>>(node_xyz, node_quat, node_sigma, t_ptr);

    // main: 4 gaussians/warp, 8 warps/block -> 32 gaussians per block
    int blocks = (N + 31) / 32;
    dyn_scf_qw_kernel<<<blocks, 256>>>(
        gs_xyz, gs_rot, node_quat, node_sem4,
        attach, ref_time, topo, (float*)d_out, N);
}